// round 11
// baseline (speedup 1.0000x reference)
#include <cuda_runtime.h>
#include <cuda_fp16.h>
#include <cstdint>
#include <math.h>

#define DIM    4096
#define B_ROWS 8192
#define EPS    1e-6f

// GEMM tiling
#define BM 128
#define BN 128
#define BK 64
#define NT 32                 // column tiles
#define MT 64                 // row tiles
#define ROWB 144              // bytes per smem row (64 fp16 = 128B data + 16B pad)
#define TILE_B (128 * ROWB)   // 18432 bytes per operand tile
#define STAGE_B (2 * TILE_B)  // Ah, Bh = 36864 bytes
#define NSTAGE 3
#define DYN_SMEM (NSTAGE * STAGE_B)  // 110592 -> 2 CTAs/SM (221KB)

// ---------------- scratch (device globals; no runtime allocation) ----------
__device__ __half g_xh[(size_t)B_ROWS * DIM];        // fp16-rounded x
__device__ __half g_whT[(size_t)DIM * DIM];          // W^T: [n][k] fp16
__device__ float g_h[(size_t)B_ROWS * DIM];
__device__ float g_psum[128 * DIM];
__device__ float g_psumsq[128 * DIM];
__device__ float g_mean[DIM];
__device__ float g_scale[DIM];

// ---------------- helpers ---------------------------------------------------
__device__ __forceinline__ uint32_t smem_u32(const void* p) {
    uint32_t a;
    asm("{ .reg .u64 t; cvta.to.shared.u64 t, %1; cvt.u32.u64 %0, t; }"
        : "=r"(a) : "l"(p));
    return a;
}

__device__ __forceinline__ uint32_t pk2(__half a, __half b) {
    return (uint32_t)__half_as_ushort(a) | ((uint32_t)__half_as_ushort(b) << 16);
}

#define CPA16(dst, src) \
    asm volatile("cp.async.cg.shared.global [%0], [%1], 16;" :: "r"(dst), "l"(src) : "memory")
#define CPA_COMMIT() asm volatile("cp.async.commit_group;" ::: "memory")
#define CPA_WAIT1()  asm volatile("cp.async.wait_group 1;" ::: "memory")
#define CPA_WAIT0()  asm volatile("cp.async.wait_group 0;" ::: "memory")

#define LDSM4(r0, r1, r2, r3, addr) \
    asm volatile("ldmatrix.sync.aligned.m8n8.x4.shared.b16 {%0,%1,%2,%3}, [%4];" \
        : "=r"(r0), "=r"(r1), "=r"(r2), "=r"(r3) : "r"(addr))

__device__ __forceinline__ void mma_fp16(float* c, const uint32_t* a, const uint32_t* b) {
    asm volatile(
        "mma.sync.aligned.m16n8k16.row.col.f32.f16.f16.f32 "
        "{%0,%1,%2,%3}, {%4,%5,%6,%7}, {%8,%9}, {%0,%1,%2,%3};"
        : "+f"(c[0]), "+f"(c[1]), "+f"(c[2]), "+f"(c[3])
        : "r"(a[0]), "r"(a[1]), "r"(a[2]), "r"(a[3]),
          "r"(b[0]), "r"(b[1]));
}

// ---------------- prologue 1: round x to fp16 -------------------------------
__global__ __launch_bounds__(256) void split_x_kernel(const float4* __restrict__ x)
{
    const size_t i = (size_t)blockIdx.x * 256 + threadIdx.x;
    const float4 v = x[i];
    uint2 H;
    H.x = pk2(__float2half_rn(v.x), __float2half_rn(v.y));
    H.y = pk2(__float2half_rn(v.z), __float2half_rn(v.w));
    ((uint2*)g_xh)[i] = H;
}

// ---------------- prologue 2: build W^T (masked, squared diag) fp16 ---------
__global__ __launch_bounds__(256) void split_w_kernel(
    const float* __restrict__ tw, const float* __restrict__ bbw)
{
    __shared__ float sw[32][33];
    const int tx = threadIdx.x & 31;
    const int ty = threadIdx.x >> 5;           // 0..7
    const int k0 = blockIdx.y * 32;
    const int n0 = blockIdx.x * 32;

    #pragma unroll
    for (int r = 0; r < 4; r++) {
        const int k = k0 + ty + r * 8;
        const int n = n0 + tx;
        const int kb = k >> 6, nb = n >> 6;
        float w = 0.0f;
        if (kb == nb)      { const float t = tw[(size_t)k * DIM + n]; w = t * t; }
        else if (kb < nb)  { w = bbw[(size_t)k * DIM + n]; }
        sw[ty + r * 8][tx] = w;
    }
    __syncthreads();
    #pragma unroll
    for (int r = 0; r < 4; r++) {
        const int n = n0 + ty + r * 8;
        const int k = k0 + tx;
        g_whT[(size_t)n * DIM + k] = __float2half_rn(sw[tx][ty + r * 8]);
    }
}

// ---------------- fp16 GEMM + fused column stats ----------------------------
// Grid (NT, MT). CTA 128x128, 128 threads (4 warps), warp tile 64x64.
// BK=64, 3-stage cp.async pipeline (1 sync/k-tile), 2 CTAs/SM.
// Warp (wid>>1 = m half, wid&1 = n half).
// Epilogue: h = c + x_init -> g_h, plus per-64-row-group column sum/sumsq
// into fixed slots g_psum/g_psumsq[rg = mt*2 + (wid>>1)] (deterministic).
__global__ __launch_bounds__(128, 2) void gemm_mma_kernel(const float* __restrict__ x_init)
{
    extern __shared__ char smc[];
    const uint32_t smb = smem_u32(smc);

    const int tid = threadIdx.x;
    const int wid = tid >> 5;
    const int lid = tid & 31;
    const int lane4 = lid >> 2;     // 0..7
    const int laneq = lid & 3;      // 0..3

    const int nt = (NT - 1) - blockIdx.x;   // heavy tiles first
    const int mt = blockIdx.y;
    const int m0 = mt * BM;
    const int n0 = nt * BN;
    const int KT = (nt + 1) * 2;    // k-tiles of 64

    const int m0w = (wid >> 1) * 64;
    const int n0w = (wid & 1) * 64;

    float c[4][8][4];
    #pragma unroll
    for (int i = 0; i < 4; i++)
        #pragma unroll
        for (int j = 0; j < 8; j++)
            #pragma unroll
            for (int q = 0; q < 4; q++)
                c[i][j][q] = 0.0f;

    // producer: 16 cp.async (16B) per thread per stage.
    // idx -> tile (0:Ah 1:Bh), row (0..127), chunk (0..7)
    auto issue_stage = [&](int kt, int s) {
        const int kof = kt * BK;
        const uint32_t sb = smb + (uint32_t)s * STAGE_B;
        #pragma unroll
        for (int it = 0; it < 16; it++) {
            const int idx  = tid + it * 128;
            const int tile = idx >> 10;
            const int row  = (idx >> 3) & 127;
            const int ch   = idx & 7;
            const __half* base = tile ? g_whT : g_xh;
            const int row0     = tile ? n0 : m0;
            const __half* src = base + (size_t)(row0 + row) * DIM + kof + ch * 8;
            const uint32_t dst = sb + (uint32_t)(tile * TILE_B + row * ROWB + ch * 16);
            CPA16(dst, src);
        }
        CPA_COMMIT();
    };

    // per-thread ldmatrix offset components (byte offsets within a tile)
    const int L = lid;
    const uint32_t a_off = (uint32_t)((m0w + (L & 15)) * ROWB + (L >> 4) * 16);
    const uint32_t b_off = (uint32_t)((n0w + ((L >> 4) & 1) * 8 + (L & 7)) * ROWB
                                      + ((L >> 3) & 1) * 16);

    // prologue: fill 2 stages (KT >= 2 always)
    issue_stage(0, 0);
    issue_stage(1, 1);

    int s  = 0;              // stage of k-tile kt
    int s2 = NSTAGE - 1;     // stage of k-tile kt+2
    for (int kt = 0; kt < KT; kt++) {
        // wait until stage kt has landed
        if (kt + 1 < KT) { CPA_WAIT1(); }
        else             { CPA_WAIT0(); }
        __syncthreads();

        // refill the slot read at iteration kt-1 (safe behind the sync)
        if (kt + 2 < KT) issue_stage(kt + 2, s2);

        const uint32_t sb  = smb + (uint32_t)s * STAGE_B;
        const uint32_t sAh = sb;
        const uint32_t sBh = sb + TILE_B;

        #pragma unroll
        for (int ks = 0; ks < 4; ks++) {
            const uint32_t ko = (uint32_t)ks * 32;   // 16 fp16 = 32B per sub-k

            // B fragments: 64 cols = 8 n8 frags via 4 ldmatrix.x4
            uint32_t bh[8][2];
            #pragma unroll
            for (int jp = 0; jp < 4; jp++) {
                const uint32_t bo = b_off + (uint32_t)jp * 16 * ROWB + ko;
                LDSM4(bh[jp*2][0], bh[jp*2][1], bh[jp*2+1][0], bh[jp*2+1][1], sBh + bo);
            }
            // stream A fragments per i; each feeds 8 mma
            #pragma unroll
            for (int i = 0; i < 4; i++) {
                const uint32_t ao = a_off + (uint32_t)i * 16 * ROWB + ko;
                uint32_t ah[4];
                LDSM4(ah[0], ah[1], ah[2], ah[3], sAh + ao);
                #pragma unroll
                for (int j = 0; j < 8; j++)
                    mma_fp16(c[i][j], ah, bh[j]);
            }
        }

        s  = (s  == NSTAGE - 1) ? 0 : s  + 1;
        s2 = (s2 == NSTAGE - 1) ? 0 : s2 + 1;
    }

    // ---- epilogue: h = c + x_init -> g_h; fused column sum / sumsq ----
    float cs[8][2], cq[8][2];
    #pragma unroll
    for (int j = 0; j < 8; j++) {
        cs[j][0] = 0.f; cs[j][1] = 0.f;
        cq[j][0] = 0.f; cq[j][1] = 0.f;
    }

    #pragma unroll
    for (int i = 0; i < 4; i++) {
        const int row = m0 + m0w + i * 16 + lane4;
        #pragma unroll
        for (int j = 0; j < 8; j++) {
            const int col = n0 + n0w + j * 8 + laneq * 2;
            const size_t o0 = (size_t)row * DIM + col;
            const size_t o1 = (size_t)(row + 8) * DIM + col;
            const float2 x0 = *(const float2*)(x_init + o0);
            const float2 x1 = *(const float2*)(x_init + o1);
            float2 v0, v1;
            v0.x = c[i][j][0] + x0.x;
            v0.y = c[i][j][1] + x0.y;
            v1.x = c[i][j][2] + x1.x;
            v1.y = c[i][j][3] + x1.y;
            *(float2*)(g_h + o0) = v0;
            *(float2*)(g_h + o1) = v1;
            cs[j][0] += v0.x + v1.x;
            cs[j][1] += v0.y + v1.y;
            cq[j][0] = fmaf(v0.x, v0.x, fmaf(v1.x, v1.x, cq[j][0]));
            cq[j][1] = fmaf(v0.y, v0.y, fmaf(v1.y, v1.y, cq[j][1]));
        }
    }

    // reduce over lane4 (8 lanes: xor 4, 8, 16); then lanes 0..3 write
    const int rg = mt * 2 + (wid >> 1);      // 64-row group id (0..127)
    #pragma unroll
    for (int j = 0; j < 8; j++) {
        #pragma unroll
        for (int b = 0; b < 2; b++) {
            float sv = cs[j][b], qv = cq[j][b];
            sv += __shfl_xor_sync(0xffffffffu, sv, 4);
            sv += __shfl_xor_sync(0xffffffffu, sv, 8);
            sv += __shfl_xor_sync(0xffffffffu, sv, 16);
            qv += __shfl_xor_sync(0xffffffffu, qv, 4);
            qv += __shfl_xor_sync(0xffffffffu, qv, 8);
            qv += __shfl_xor_sync(0xffffffffu, qv, 16);
            if (lane4 == 0) {
                const int col = n0 + n0w + j * 8 + laneq * 2 + b;
                g_psum[rg * DIM + col]   = sv;
                g_psumsq[rg * DIM + col] = qv;
            }
        }
    }
}

// ---------------- stats stage 2: finalize mean / scale ----------------------
__global__ __launch_bounds__(256) void stats2_kernel()
{
    const int col = blockIdx.x * 256 + threadIdx.x;
    float s = 0.0f, q = 0.0f;
    #pragma unroll 8
    for (int rg = 0; rg < 128; rg++) {
        s += g_psum[rg * DIM + col];
        q += g_psumsq[rg * DIM + col];
    }
    const float inv_n = 1.0f / (float)B_ROWS;
    const float mean  = s * inv_n;
    float var = q * inv_n - mean * mean;
    var = fmaxf(var, 0.0f);
    g_mean[col]  = mean;
    g_scale[col] = 1.0f / (sqrtf(var) + EPS);
}

// ---------------- normalize + sigmoid ---------------------------------------
__global__ __launch_bounds__(256) void final_kernel(float* __restrict__ out)
{
    const int row  = blockIdx.y;
    const int col  = (blockIdx.x * 256 + threadIdx.x) * 4;
    const size_t off = (size_t)row * DIM + col;

    const float4 h  = *(const float4*)(g_h + off);
    const float4 mu = *(const float4*)(g_mean + col);
    const float4 sc = *(const float4*)(g_scale + col);

    float4 o;
    o.x = 1.0f / (1.0f + expf(-(h.x - mu.x) * sc.x));
    o.y = 1.0f / (1.0f + expf(-(h.y - mu.y) * sc.y));
    o.z = 1.0f / (1.0f + expf(-(h.z - mu.z) * sc.z));
    o.w = 1.0f / (1.0f + expf(-(h.w - mu.w) * sc.w));
    *(float4*)(out + off) = o;
}

// ---------------- launcher ---------------------------------------------------
extern "C" void kernel_launch(void* const* d_in, const int* in_sizes, int n_in,
                              void* d_out, int out_size)
{
    const float* x   = (const float*)d_in[0];
    const float* xi  = (const float*)d_in[1];
    const float* tw  = (const float*)d_in[2];
    const float* bbw = (const float*)d_in[3];
    float* out = (float*)d_out;

    cudaFuncSetAttribute(gemm_mma_kernel,
                         cudaFuncAttributeMaxDynamicSharedMemorySize, DYN_SMEM);

    split_x_kernel<<<(B_ROWS * DIM) / (256 * 4), 256>>>((const float4*)x);
    split_w_kernel<<<dim3(DIM / 32, DIM / 32), 256>>>(tw, bbw);
    gemm_mma_kernel<<<dim3(NT, MT), 128, DYN_SMEM>>>(xi);
    stats2_kernel<<<DIM / 256, 256>>>();
    final_kernel<<<dim3(DIM / (256 * 4), B_ROWS), 256>>>(out);
}

// round 12
// speedup vs baseline: 1.0690x; 1.0690x over previous
#include <cuda_runtime.h>
#include <cuda_fp16.h>
#include <cstdint>
#include <math.h>

#define DIM    4096
#define B_ROWS 8192
#define EPS    1e-6f

// GEMM tiling
#define BM 128
#define BN 128
#define BK 32
#define NT 32                 // column tiles
#define MT 64                 // row tiles
#define ROWB 80               // bytes per smem row (32 fp16 = 64B data + 16B pad)
#define TILE_B (128 * ROWB)   // 10240 bytes per operand tile
#define STAGE_B (2 * TILE_B)  // Ah, Bh = 20480 bytes
#define NSTAGE 4
#define DYN_SMEM (NSTAGE * STAGE_B)  // 81920 -> 2 CTAs/SM (164KB)

// ---------------- scratch (device globals; no runtime allocation) ----------
__device__ __half g_xh[(size_t)B_ROWS * DIM];        // fp16-rounded x
__device__ __half g_whT[(size_t)DIM * DIM];          // W^T: [n][k] fp16
__device__ float g_h[(size_t)B_ROWS * DIM];
__device__ float g_psum[128 * DIM];
__device__ float g_psumsq[128 * DIM];
__device__ float g_psum2[8 * DIM];
__device__ float g_psumsq2[8 * DIM];
__device__ float g_mean[DIM];
__device__ float g_scale[DIM];

// ---------------- helpers ---------------------------------------------------
__device__ __forceinline__ uint32_t smem_u32(const void* p) {
    uint32_t a;
    asm("{ .reg .u64 t; cvta.to.shared.u64 t, %1; cvt.u32.u64 %0, t; }"
        : "=r"(a) : "l"(p));
    return a;
}

__device__ __forceinline__ uint32_t pk2(__half a, __half b) {
    return (uint32_t)__half_as_ushort(a) | ((uint32_t)__half_as_ushort(b) << 16);
}

#define CPA16(dst, src) \
    asm volatile("cp.async.cg.shared.global [%0], [%1], 16;" :: "r"(dst), "l"(src) : "memory")
#define CPA_COMMIT() asm volatile("cp.async.commit_group;" ::: "memory")
#define CPA_WAIT2()  asm volatile("cp.async.wait_group 2;" ::: "memory")
#define CPA_WAIT1()  asm volatile("cp.async.wait_group 1;" ::: "memory")
#define CPA_WAIT0()  asm volatile("cp.async.wait_group 0;" ::: "memory")

#define LDSM4(r0, r1, r2, r3, addr) \
    asm volatile("ldmatrix.sync.aligned.m8n8.x4.shared.b16 {%0,%1,%2,%3}, [%4];" \
        : "=r"(r0), "=r"(r1), "=r"(r2), "=r"(r3) : "r"(addr))

__device__ __forceinline__ void mma_fp16(float* c, const uint32_t* a, const uint32_t* b) {
    asm volatile(
        "mma.sync.aligned.m16n8k16.row.col.f32.f16.f16.f32 "
        "{%0,%1,%2,%3}, {%4,%5,%6,%7}, {%8,%9}, {%0,%1,%2,%3};"
        : "+f"(c[0]), "+f"(c[1]), "+f"(c[2]), "+f"(c[3])
        : "r"(a[0]), "r"(a[1]), "r"(a[2]), "r"(a[3]),
          "r"(b[0]), "r"(b[1]));
}

// ---------------- prologue 1: round x to fp16 -------------------------------
__global__ __launch_bounds__(256) void split_x_kernel(const float4* __restrict__ x)
{
    const size_t i = (size_t)blockIdx.x * 256 + threadIdx.x;
    const float4 v = x[i];
    uint2 H;
    H.x = pk2(__float2half_rn(v.x), __float2half_rn(v.y));
    H.y = pk2(__float2half_rn(v.z), __float2half_rn(v.w));
    ((uint2*)g_xh)[i] = H;
}

// ---------------- prologue 2: build W^T (masked, squared diag) fp16 ---------
__global__ __launch_bounds__(256) void split_w_kernel(
    const float* __restrict__ tw, const float* __restrict__ bbw)
{
    __shared__ float sw[32][33];
    const int tx = threadIdx.x & 31;
    const int ty = threadIdx.x >> 5;           // 0..7
    const int k0 = blockIdx.y * 32;
    const int n0 = blockIdx.x * 32;

    #pragma unroll
    for (int r = 0; r < 4; r++) {
        const int k = k0 + ty + r * 8;
        const int n = n0 + tx;
        const int kb = k >> 6, nb = n >> 6;
        float w = 0.0f;
        if (kb == nb)      { const float t = tw[(size_t)k * DIM + n]; w = t * t; }
        else if (kb < nb)  { w = bbw[(size_t)k * DIM + n]; }
        sw[ty + r * 8][tx] = w;
    }
    __syncthreads();
    #pragma unroll
    for (int r = 0; r < 4; r++) {
        const int n = n0 + ty + r * 8;
        const int k = k0 + tx;
        g_whT[(size_t)n * DIM + k] = __float2half_rn(sw[tx][ty + r * 8]);
    }
}

// ---------------- fp16 GEMM + fused column stats ----------------------------
// Grid (NT, MT). CTA 128x128, 128 threads (4 warps), warp tile 64x64.
// BK=32, 4-stage cp.async pipeline (1 sync/k-tile), 2 CTAs/SM.
// Warp (wid>>1 = m half, wid&1 = n half).
// Epilogue: h = c + x_init -> g_h, plus per-64-row-group column sum/sumsq
// into fixed slots g_psum/g_psumsq[rg = mt*2 + (wid>>1)] (deterministic).
__global__ __launch_bounds__(128, 2) void gemm_mma_kernel(const float* __restrict__ x_init)
{
    extern __shared__ char smc[];
    const uint32_t smb = smem_u32(smc);

    const int tid = threadIdx.x;
    const int wid = tid >> 5;
    const int lid = tid & 31;
    const int lane4 = lid >> 2;     // 0..7
    const int laneq = lid & 3;      // 0..3

    const int nt = (NT - 1) - blockIdx.x;   // heavy tiles first
    const int mt = blockIdx.y;
    const int m0 = mt * BM;
    const int n0 = nt * BN;
    const int KT = (nt + 1) * 4;    // k-tiles of 32

    const int m0w = (wid >> 1) * 64;
    const int n0w = (wid & 1) * 64;

    float c[4][8][4];
    #pragma unroll
    for (int i = 0; i < 4; i++)
        #pragma unroll
        for (int j = 0; j < 8; j++)
            #pragma unroll
            for (int q = 0; q < 4; q++)
                c[i][j][q] = 0.0f;

    // producer: 8 cp.async (16B) per thread per stage.
    // idx -> tile (0:Ah 1:Bh), row (0..127), chunk (0..3)
    auto issue_stage = [&](int kt, int s) {
        const int kof = kt * BK;
        const uint32_t sb = smb + (uint32_t)s * STAGE_B;
        #pragma unroll
        for (int it = 0; it < 8; it++) {
            const int idx  = tid + it * 128;
            const int tile = idx >> 9;
            const int row  = (idx >> 2) & 127;
            const int ch   = idx & 3;
            const __half* base = tile ? g_whT : g_xh;
            const int row0     = tile ? n0 : m0;
            const __half* src = base + (size_t)(row0 + row) * DIM + kof + ch * 8;
            const uint32_t dst = sb + (uint32_t)(tile * TILE_B + row * ROWB + ch * 16);
            CPA16(dst, src);
        }
        CPA_COMMIT();
    };

    // per-thread ldmatrix offset components (byte offsets within a tile)
    const int L = lid;
    const uint32_t a_off = (uint32_t)((m0w + (L & 15)) * ROWB + (L >> 4) * 16);
    const uint32_t b_off = (uint32_t)((n0w + ((L >> 4) & 1) * 8 + (L & 7)) * ROWB
                                      + ((L >> 3) & 1) * 16);

    // prologue: fill 3 stages (KT >= 4 always)
    issue_stage(0, 0);
    issue_stage(1, 1);
    issue_stage(2, 2);

    int s  = 0;              // stage of k-tile kt
    int s3 = NSTAGE - 1;     // stage of k-tile kt+3
    for (int kt = 0; kt < KT; kt++) {
        // wait until stage kt has landed (pending groups = min(KT-kt-1, 2))
        const int rem = KT - kt - 1;
        if      (rem >= 2) { CPA_WAIT2(); }
        else if (rem == 1) { CPA_WAIT1(); }
        else               { CPA_WAIT0(); }
        __syncthreads();

        // refill the slot read at iteration kt-1 (safe behind the sync)
        if (kt + 3 < KT) issue_stage(kt + 3, s3);

        const uint32_t sb  = smb + (uint32_t)s * STAGE_B;
        const uint32_t sAh = sb;
        const uint32_t sBh = sb + TILE_B;

        #pragma unroll
        for (int ks = 0; ks < 2; ks++) {
            const uint32_t ko = (uint32_t)ks * 32;

            // B fragments: 64 cols = 8 n8 frags via 4 ldmatrix.x4
            uint32_t bh[8][2];
            #pragma unroll
            for (int jp = 0; jp < 4; jp++) {
                const uint32_t bo = b_off + (uint32_t)jp * 16 * ROWB + ko;
                LDSM4(bh[jp*2][0], bh[jp*2][1], bh[jp*2+1][0], bh[jp*2+1][1], sBh + bo);
            }
            // stream A fragments per i; each feeds 8 mma
            #pragma unroll
            for (int i = 0; i < 4; i++) {
                const uint32_t ao = a_off + (uint32_t)i * 16 * ROWB + ko;
                uint32_t ah[4];
                LDSM4(ah[0], ah[1], ah[2], ah[3], sAh + ao);
                #pragma unroll
                for (int j = 0; j < 8; j++)
                    mma_fp16(c[i][j], ah, bh[j]);
            }
        }

        s  = (s  == NSTAGE - 1) ? 0 : s  + 1;
        s3 = (s3 == NSTAGE - 1) ? 0 : s3 + 1;
    }

    // ---- epilogue: h = c + x_init -> g_h; fused column sum / sumsq ----
    float cs[8][2], cq[8][2];
    #pragma unroll
    for (int j = 0; j < 8; j++) {
        cs[j][0] = 0.f; cs[j][1] = 0.f;
        cq[j][0] = 0.f; cq[j][1] = 0.f;
    }

    #pragma unroll
    for (int i = 0; i < 4; i++) {
        const int row = m0 + m0w + i * 16 + lane4;
        #pragma unroll
        for (int j = 0; j < 8; j++) {
            const int col = n0 + n0w + j * 8 + laneq * 2;
            const size_t o0 = (size_t)row * DIM + col;
            const size_t o1 = (size_t)(row + 8) * DIM + col;
            const float2 x0 = *(const float2*)(x_init + o0);
            const float2 x1 = *(const float2*)(x_init + o1);
            float2 v0, v1;
            v0.x = c[i][j][0] + x0.x;
            v0.y = c[i][j][1] + x0.y;
            v1.x = c[i][j][2] + x1.x;
            v1.y = c[i][j][3] + x1.y;
            *(float2*)(g_h + o0) = v0;
            *(float2*)(g_h + o1) = v1;
            cs[j][0] += v0.x + v1.x;
            cs[j][1] += v0.y + v1.y;
            cq[j][0] = fmaf(v0.x, v0.x, fmaf(v1.x, v1.x, cq[j][0]));
            cq[j][1] = fmaf(v0.y, v0.y, fmaf(v1.y, v1.y, cq[j][1]));
        }
    }

    // reduce over lane4 (8 lanes: xor 4, 8, 16); then lanes 0..3 write
    const int rg = mt * 2 + (wid >> 1);      // 64-row group id (0..127)
    #pragma unroll
    for (int j = 0; j < 8; j++) {
        #pragma unroll
        for (int b = 0; b < 2; b++) {
            float sv = cs[j][b], qv = cq[j][b];
            sv += __shfl_xor_sync(0xffffffffu, sv, 4);
            sv += __shfl_xor_sync(0xffffffffu, sv, 8);
            sv += __shfl_xor_sync(0xffffffffu, sv, 16);
            qv += __shfl_xor_sync(0xffffffffu, qv, 4);
            qv += __shfl_xor_sync(0xffffffffu, qv, 8);
            qv += __shfl_xor_sync(0xffffffffu, qv, 16);
            if (lane4 == 0) {
                const int col = n0 + n0w + j * 8 + laneq * 2 + b;
                g_psum[rg * DIM + col]   = sv;
                g_psumsq[rg * DIM + col] = qv;
            }
        }
    }
}

// ---------------- stats 2a: reduce 128 row-groups -> 8 ----------------------
// grid (16, 8), block 256: block (bx, by) sums rgs [by*16, by*16+16).
__global__ __launch_bounds__(256) void stats2a_kernel()
{
    const int col = blockIdx.x * 256 + threadIdx.x;
    const int g   = blockIdx.y;                    // 0..7
    float s = 0.0f, q = 0.0f;
    #pragma unroll
    for (int r = 0; r < 16; r++) {
        const int rg = g * 16 + r;
        s += g_psum[rg * DIM + col];
        q += g_psumsq[rg * DIM + col];
    }
    g_psum2[g * DIM + col]   = s;
    g_psumsq2[g * DIM + col] = q;
}

// ---------------- stats 2b: finalize mean / scale ---------------------------
__global__ __launch_bounds__(256) void stats2b_kernel()
{
    const int col = blockIdx.x * 256 + threadIdx.x;
    float s = 0.0f, q = 0.0f;
    #pragma unroll
    for (int g = 0; g < 8; g++) {
        s += g_psum2[g * DIM + col];
        q += g_psumsq2[g * DIM + col];
    }
    const float inv_n = 1.0f / (float)B_ROWS;
    const float mean  = s * inv_n;
    float var = q * inv_n - mean * mean;
    var = fmaxf(var, 0.0f);
    g_mean[col]  = mean;
    g_scale[col] = 1.0f / (sqrtf(var) + EPS);
}

// ---------------- normalize + sigmoid ---------------------------------------
__global__ __launch_bounds__(256) void final_kernel(float* __restrict__ out)
{
    const int row  = blockIdx.y;
    const int col  = (blockIdx.x * 256 + threadIdx.x) * 4;
    const size_t off = (size_t)row * DIM + col;

    const float4 h  = *(const float4*)(g_h + off);
    const float4 mu = *(const float4*)(g_mean + col);
    const float4 sc = *(const float4*)(g_scale + col);

    float4 o;
    o.x = 1.0f / (1.0f + expf(-(h.x - mu.x) * sc.x));
    o.y = 1.0f / (1.0f + expf(-(h.y - mu.y) * sc.y));
    o.z = 1.0f / (1.0f + expf(-(h.z - mu.z) * sc.z));
    o.w = 1.0f / (1.0f + expf(-(h.w - mu.w) * sc.w));
    *(float4*)(out + off) = o;
}

// ---------------- launcher ---------------------------------------------------
extern "C" void kernel_launch(void* const* d_in, const int* in_sizes, int n_in,
                              void* d_out, int out_size)
{
    const float* x   = (const float*)d_in[0];
    const float* xi  = (const float*)d_in[1];
    const float* tw  = (const float*)d_in[2];
    const float* bbw = (const float*)d_in[3];
    float* out = (float*)d_out;

    cudaFuncSetAttribute(gemm_mma_kernel,
                         cudaFuncAttributeMaxDynamicSharedMemorySize, DYN_SMEM);

    split_x_kernel<<<(B_ROWS * DIM) / (256 * 4), 256>>>((const float4*)x);
    split_w_kernel<<<dim3(DIM / 32, DIM / 32), 256>>>(tw, bbw);
    gemm_mma_kernel<<<dim3(NT, MT), 128, DYN_SMEM>>>(xi);
    stats2a_kernel<<<dim3(16, 8), 256>>>();
    stats2b_kernel<<<16, 256>>>();
    final_kernel<<<dim3(DIM / (256 * 4), B_ROWS), 256>>>(out);
}

// round 14
// speedup vs baseline: 1.0740x; 1.0047x over previous
#include <cuda_runtime.h>
#include <cuda_fp16.h>
#include <cstdint>
#include <math.h>

#define DIM    4096
#define B_ROWS 8192
#define EPS    1e-6f

// GEMM tiling
#define BM 128
#define BN 128
#define BK 32
#define NT 32                 // column tiles
#define MT 64                 // row tiles
#define ROWB 80               // bytes per smem row (32 fp16 = 64B data + 16B pad)
#define TILE_B (128 * ROWB)   // 10240 bytes per operand tile
#define STAGE_B (2 * TILE_B)  // Ah, Bh = 20480 bytes
#define NSTAGE 4
#define DYN_SMEM (NSTAGE * STAGE_B)  // 81920 -> 2 CTAs/SM (164KB)

// ---------------- scratch (device globals; no runtime allocation) ----------
__device__ __half g_xh[(size_t)B_ROWS * DIM];        // fp16-rounded x
__device__ __half g_whT[(size_t)DIM * DIM];          // W^T: [n][k] fp16
__device__ __half g_hh[(size_t)B_ROWS * DIM];        // h stored fp16 (stats from f32)
__device__ float g_psum[128 * DIM];
__device__ float g_psumsq[128 * DIM];
__device__ float g_psum2[8 * DIM];
__device__ float g_psumsq2[8 * DIM];
__device__ float g_mean[DIM];
__device__ float g_scale[DIM];

// ---------------- helpers ---------------------------------------------------
__device__ __forceinline__ uint32_t smem_u32(const void* p) {
    uint32_t a;
    asm("{ .reg .u64 t; cvta.to.shared.u64 t, %1; cvt.u32.u64 %0, t; }"
        : "=r"(a) : "l"(p));
    return a;
}

__device__ __forceinline__ uint32_t pk2(__half a, __half b) {
    return (uint32_t)__half_as_ushort(a) | ((uint32_t)__half_as_ushort(b) << 16);
}

#define CPA16(dst, src) \
    asm volatile("cp.async.cg.shared.global [%0], [%1], 16;" :: "r"(dst), "l"(src) : "memory")
#define CPA_COMMIT() asm volatile("cp.async.commit_group;" ::: "memory")
#define CPA_WAIT2()  asm volatile("cp.async.wait_group 2;" ::: "memory")
#define CPA_WAIT1()  asm volatile("cp.async.wait_group 1;" ::: "memory")
#define CPA_WAIT0()  asm volatile("cp.async.wait_group 0;" ::: "memory")

#define LDSM4(r0, r1, r2, r3, addr) \
    asm volatile("ldmatrix.sync.aligned.m8n8.x4.shared.b16 {%0,%1,%2,%3}, [%4];" \
        : "=r"(r0), "=r"(r1), "=r"(r2), "=r"(r3) : "r"(addr))

__device__ __forceinline__ void mma_fp16(float* c, const uint32_t* a, const uint32_t* b) {
    asm volatile(
        "mma.sync.aligned.m16n8k16.row.col.f32.f16.f16.f32 "
        "{%0,%1,%2,%3}, {%4,%5,%6,%7}, {%8,%9}, {%0,%1,%2,%3};"
        : "+f"(c[0]), "+f"(c[1]), "+f"(c[2]), "+f"(c[3])
        : "r"(a[0]), "r"(a[1]), "r"(a[2]), "r"(a[3]),
          "r"(b[0]), "r"(b[1]));
}

// ---------------- prologue 1: round x to fp16 -------------------------------
__global__ __launch_bounds__(256) void split_x_kernel(const float4* __restrict__ x)
{
    const size_t i = (size_t)blockIdx.x * 256 + threadIdx.x;
    const float4 v = x[i];
    uint2 H;
    H.x = pk2(__float2half_rn(v.x), __float2half_rn(v.y));
    H.y = pk2(__float2half_rn(v.z), __float2half_rn(v.w));
    ((uint2*)g_xh)[i] = H;
}

// ---------------- prologue 2: build W^T (masked, squared diag) fp16 ---------
__global__ __launch_bounds__(256) void split_w_kernel(
    const float* __restrict__ tw, const float* __restrict__ bbw)
{
    __shared__ float sw[32][33];
    const int tx = threadIdx.x & 31;
    const int ty = threadIdx.x >> 5;           // 0..7
    const int k0 = blockIdx.y * 32;
    const int n0 = blockIdx.x * 32;

    #pragma unroll
    for (int r = 0; r < 4; r++) {
        const int k = k0 + ty + r * 8;
        const int n = n0 + tx;
        const int kb = k >> 6, nb = n >> 6;
        float w = 0.0f;
        if (kb == nb)      { const float t = tw[(size_t)k * DIM + n]; w = t * t; }
        else if (kb < nb)  { w = bbw[(size_t)k * DIM + n]; }
        sw[ty + r * 8][tx] = w;
    }
    __syncthreads();
    #pragma unroll
    for (int r = 0; r < 4; r++) {
        const int n = n0 + ty + r * 8;
        const int k = k0 + tx;
        g_whT[(size_t)n * DIM + k] = __float2half_rn(sw[tx][ty + r * 8]);
    }
}

// ---------------- fp16 GEMM + fused column stats ----------------------------
// Grid (NT, MT). CTA 128x128, 128 threads (4 warps), warp tile 64x64.
// BK=32, 4-stage cp.async pipeline (1 sync/k-tile), 2 CTAs/SM.
// Warp (wid>>1 = m half, wid&1 = n half).
// Epilogue: h = c + x_init (f32) -> stats (f32) + g_hh (fp16), fixed slots
// g_psum/g_psumsq[rg = mt*2 + (wid>>1)] (deterministic).
__global__ __launch_bounds__(128, 2) void gemm_mma_kernel(const float* __restrict__ x_init)
{
    extern __shared__ char smc[];
    const uint32_t smb = smem_u32(smc);

    const int tid = threadIdx.x;
    const int wid = tid >> 5;
    const int lid = tid & 31;
    const int lane4 = lid >> 2;     // 0..7
    const int laneq = lid & 3;      // 0..3

    const int nt = (NT - 1) - blockIdx.x;   // heavy tiles first
    const int mt = blockIdx.y;
    const int m0 = mt * BM;
    const int n0 = nt * BN;
    const int KT = (nt + 1) * 4;    // k-tiles of 32

    const int m0w = (wid >> 1) * 64;
    const int n0w = (wid & 1) * 64;

    float c[4][8][4];
    #pragma unroll
    for (int i = 0; i < 4; i++)
        #pragma unroll
        for (int j = 0; j < 8; j++)
            #pragma unroll
            for (int q = 0; q < 4; q++)
                c[i][j][q] = 0.0f;

    // producer: 8 cp.async (16B) per thread per stage.
    // idx -> tile (0:Ah 1:Bh), row (0..127), chunk (0..3)
    auto issue_stage = [&](int kt, int s) {
        const int kof = kt * BK;
        const uint32_t sb = smb + (uint32_t)s * STAGE_B;
        #pragma unroll
        for (int it = 0; it < 8; it++) {
            const int idx  = tid + it * 128;
            const int tile = idx >> 9;
            const int row  = (idx >> 2) & 127;
            const int ch   = idx & 3;
            const __half* base = tile ? g_whT : g_xh;
            const int row0     = tile ? n0 : m0;
            const __half* src = base + (size_t)(row0 + row) * DIM + kof + ch * 8;
            const uint32_t dst = sb + (uint32_t)(tile * TILE_B + row * ROWB + ch * 16);
            CPA16(dst, src);
        }
        CPA_COMMIT();
    };

    // per-thread ldmatrix offset components (byte offsets within a tile)
    const int L = lid;
    const uint32_t a_off = (uint32_t)((m0w + (L & 15)) * ROWB + (L >> 4) * 16);
    const uint32_t b_off = (uint32_t)((n0w + ((L >> 4) & 1) * 8 + (L & 7)) * ROWB
                                      + ((L >> 3) & 1) * 16);

    // prologue: fill 3 stages (KT >= 4 always)
    issue_stage(0, 0);
    issue_stage(1, 1);
    issue_stage(2, 2);

    int s  = 0;              // stage of k-tile kt
    int s3 = NSTAGE - 1;     // stage of k-tile kt+3
    for (int kt = 0; kt < KT; kt++) {
        // wait until stage kt has landed (pending groups = min(KT-kt-1, 2))
        const int rem = KT - kt - 1;
        if      (rem >= 2) { CPA_WAIT2(); }
        else if (rem == 1) { CPA_WAIT1(); }
        else               { CPA_WAIT0(); }
        __syncthreads();

        // refill the slot read at iteration kt-1 (safe behind the sync)
        if (kt + 3 < KT) issue_stage(kt + 3, s3);

        const uint32_t sb  = smb + (uint32_t)s * STAGE_B;
        const uint32_t sAh = sb;
        const uint32_t sBh = sb + TILE_B;

        #pragma unroll
        for (int ks = 0; ks < 2; ks++) {
            const uint32_t ko = (uint32_t)ks * 32;

            // B fragments: 64 cols = 8 n8 frags via 4 ldmatrix.x4
            uint32_t bh[8][2];
            #pragma unroll
            for (int jp = 0; jp < 4; jp++) {
                const uint32_t bo = b_off + (uint32_t)jp * 16 * ROWB + ko;
                LDSM4(bh[jp*2][0], bh[jp*2][1], bh[jp*2+1][0], bh[jp*2+1][1], sBh + bo);
            }
            // stream A fragments per i; each feeds 8 mma
            #pragma unroll
            for (int i = 0; i < 4; i++) {
                const uint32_t ao = a_off + (uint32_t)i * 16 * ROWB + ko;
                uint32_t ah[4];
                LDSM4(ah[0], ah[1], ah[2], ah[3], sAh + ao);
                #pragma unroll
                for (int j = 0; j < 8; j++)
                    mma_fp16(c[i][j], ah, bh[j]);
            }
        }

        s  = (s  == NSTAGE - 1) ? 0 : s  + 1;
        s3 = (s3 == NSTAGE - 1) ? 0 : s3 + 1;
    }

    // ---- epilogue: h = c + x_init (f32); stats in f32; store h as fp16 ----
    float cs[8][2], cq[8][2];
    #pragma unroll
    for (int j = 0; j < 8; j++) {
        cs[j][0] = 0.f; cs[j][1] = 0.f;
        cq[j][0] = 0.f; cq[j][1] = 0.f;
    }

    #pragma unroll
    for (int i = 0; i < 4; i++) {
        const int row = m0 + m0w + i * 16 + lane4;
        #pragma unroll
        for (int j = 0; j < 8; j++) {
            const int col = n0 + n0w + j * 8 + laneq * 2;
            const size_t o0 = (size_t)row * DIM + col;
            const size_t o1 = (size_t)(row + 8) * DIM + col;
            const float2 x0 = *(const float2*)(x_init + o0);
            const float2 x1 = *(const float2*)(x_init + o1);
            float2 v0, v1;
            v0.x = c[i][j][0] + x0.x;
            v0.y = c[i][j][1] + x0.y;
            v1.x = c[i][j][2] + x1.x;
            v1.y = c[i][j][3] + x1.y;
            *(__half2*)(g_hh + o0) = __floats2half2_rn(v0.x, v0.y);
            *(__half2*)(g_hh + o1) = __floats2half2_rn(v1.x, v1.y);
            cs[j][0] += v0.x + v1.x;
            cs[j][1] += v0.y + v1.y;
            cq[j][0] = fmaf(v0.x, v0.x, fmaf(v1.x, v1.x, cq[j][0]));
            cq[j][1] = fmaf(v0.y, v0.y, fmaf(v1.y, v1.y, cq[j][1]));
        }
    }

    // reduce over lane4 (8 lanes: xor 4, 8, 16); then lanes 0..3 write
    const int rg = mt * 2 + (wid >> 1);      // 64-row group id (0..127)
    #pragma unroll
    for (int j = 0; j < 8; j++) {
        #pragma unroll
        for (int b = 0; b < 2; b++) {
            float sv = cs[j][b], qv = cq[j][b];
            sv += __shfl_xor_sync(0xffffffffu, sv, 4);
            sv += __shfl_xor_sync(0xffffffffu, sv, 8);
            sv += __shfl_xor_sync(0xffffffffu, sv, 16);
            qv += __shfl_xor_sync(0xffffffffu, qv, 4);
            qv += __shfl_xor_sync(0xffffffffu, qv, 8);
            qv += __shfl_xor_sync(0xffffffffu, qv, 16);
            if (lane4 == 0) {
                const int col = n0 + n0w + j * 8 + laneq * 2 + b;
                g_psum[rg * DIM + col]   = sv;
                g_psumsq[rg * DIM + col] = qv;
            }
        }
    }
}

// ---------------- stats 2a: reduce 128 row-groups -> 8 ----------------------
__global__ __launch_bounds__(256) void stats2a_kernel()
{
    const int col = blockIdx.x * 256 + threadIdx.x;
    const int g   = blockIdx.y;                    // 0..7
    float s = 0.0f, q = 0.0f;
    #pragma unroll
    for (int r = 0; r < 16; r++) {
        const int rg = g * 16 + r;
        s += g_psum[rg * DIM + col];
        q += g_psumsq[rg * DIM + col];
    }
    g_psum2[g * DIM + col]   = s;
    g_psumsq2[g * DIM + col] = q;
}

// ---------------- stats 2b: finalize mean / scale ---------------------------
__global__ __launch_bounds__(256) void stats2b_kernel()
{
    const int col = blockIdx.x * 256 + threadIdx.x;
    float s = 0.0f, q = 0.0f;
    #pragma unroll
    for (int g = 0; g < 8; g++) {
        s += g_psum2[g * DIM + col];
        q += g_psumsq2[g * DIM + col];
    }
    const float inv_n = 1.0f / (float)B_ROWS;
    const float mean  = s * inv_n;
    float var = q * inv_n - mean * mean;
    var = fmaxf(var, 0.0f);
    g_mean[col]  = mean;
    g_scale[col] = 1.0f / (sqrtf(var) + EPS);
}

// ---------------- normalize + sigmoid (h read as fp16) ----------------------
__global__ __launch_bounds__(256) void final_kernel(float* __restrict__ out)
{
    const int row  = blockIdx.y;
    const int col  = (blockIdx.x * 256 + threadIdx.x) * 4;
    const size_t off = (size_t)row * DIM + col;

    const uint2 raw = *(const uint2*)(g_hh + off);
    const float2 h01 = __half22float2(*(const __half2*)&raw.x);
    const float2 h23 = __half22float2(*(const __half2*)&raw.y);
    const float4 mu = *(const float4*)(g_mean + col);
    const float4 sc = *(const float4*)(g_scale + col);

    float4 o;
    o.x = 1.0f / (1.0f + expf(-(h01.x - mu.x) * sc.x));
    o.y = 1.0f / (1.0f + expf(-(h01.y - mu.y) * sc.y));
    o.z = 1.0f / (1.0f + expf(-(h23.x - mu.z) * sc.z));
    o.w = 1.0f / (1.0f + expf(-(h23.y - mu.w) * sc.w));
    *(float4*)(out + off) = o;
}

// ---------------- launcher ---------------------------------------------------
extern "C" void kernel_launch(void* const* d_in, const int* in_sizes, int n_in,
                              void* d_out, int out_size)
{
    const float* x   = (const float*)d_in[0];
    const float* xi  = (const float*)d_in[1];
    const float* tw  = (const float*)d_in[2];
    const float* bbw = (const float*)d_in[3];
    float* out = (float*)d_out;

    cudaFuncSetAttribute(gemm_mma_kernel,
                         cudaFuncAttributeMaxDynamicSharedMemorySize, DYN_SMEM);

    split_x_kernel<<<(B_ROWS * DIM) / (256 * 4), 256>>>((const float4*)x);
    split_w_kernel<<<dim3(DIM / 32, DIM / 32), 256>>>(tw, bbw);
    gemm_mma_kernel<<<dim3(NT, MT), 128, DYN_SMEM>>>(xi);
    stats2a_kernel<<<dim3(16, 8), 256>>>();
    stats2b_kernel<<<16, 256>>>();
    final_kernel<<<dim3(DIM / (256 * 4), B_ROWS), 256>>>(out);
}

// round 16
// speedup vs baseline: 1.0799x; 1.0055x over previous
#include <cuda_runtime.h>
#include <cuda_fp16.h>
#include <cstdint>
#include <math.h>

#define DIM    4096
#define B_ROWS 8192
#define EPS    1e-6f

// GEMM tiling
#define BM 128
#define BN 128
#define BK 32
#define NT 32                 // column tiles
#define MT 64                 // row tiles
#define ROWB 80               // bytes per smem row (32 fp16 = 64B data + 16B pad)
#define TILE_B (128 * ROWB)   // 10240 bytes per operand tile
#define STAGE_B (2 * TILE_B)  // Ah, Bh = 20480 bytes
#define NSTAGE 4
#define DYN_SMEM (NSTAGE * STAGE_B)  // 81920 -> 2 CTAs/SM (164KB)

// x-blocks in merged prologue: one float4 per thread
#define XBLOCKS ((B_ROWS * DIM) / (256 * 4))   // 32768
#define WBLOCKS ((DIM / 32) * (DIM / 32))      // 16384

// ---------------- scratch (device globals; no runtime allocation) ----------
__device__ __half g_xh[(size_t)B_ROWS * DIM];        // fp16-rounded x
__device__ __half g_whT[(size_t)DIM * DIM];          // W^T: [n][k] fp16
__device__ __half g_hh[(size_t)B_ROWS * DIM];        // h stored fp16 (stats from f32)
__device__ float g_psum[128 * DIM];
__device__ float g_psumsq[128 * DIM];
__device__ float g_psum2[8 * DIM];
__device__ float g_psumsq2[8 * DIM];
__device__ float g_mean[DIM];
__device__ float g_scale[DIM];

// ---------------- helpers ---------------------------------------------------
__device__ __forceinline__ uint32_t smem_u32(const void* p) {
    uint32_t a;
    asm("{ .reg .u64 t; cvta.to.shared.u64 t, %1; cvt.u32.u64 %0, t; }"
        : "=r"(a) : "l"(p));
    return a;
}

__device__ __forceinline__ uint32_t pk2(__half a, __half b) {
    return (uint32_t)__half_as_ushort(a) | ((uint32_t)__half_as_ushort(b) << 16);
}

#define CPA16(dst, src) \
    asm volatile("cp.async.cg.shared.global [%0], [%1], 16;" :: "r"(dst), "l"(src) : "memory")
#define CPA_COMMIT() asm volatile("cp.async.commit_group;" ::: "memory")
#define CPA_WAIT2()  asm volatile("cp.async.wait_group 2;" ::: "memory")
#define CPA_WAIT1()  asm volatile("cp.async.wait_group 1;" ::: "memory")
#define CPA_WAIT0()  asm volatile("cp.async.wait_group 0;" ::: "memory")

#define LDSM4(r0, r1, r2, r3, addr) \
    asm volatile("ldmatrix.sync.aligned.m8n8.x4.shared.b16 {%0,%1,%2,%3}, [%4];" \
        : "=r"(r0), "=r"(r1), "=r"(r2), "=r"(r3) : "r"(addr))

__device__ __forceinline__ void mma_fp16(float* c, const uint32_t* a, const uint32_t* b) {
    asm volatile(
        "mma.sync.aligned.m16n8k16.row.col.f32.f16.f16.f32 "
        "{%0,%1,%2,%3}, {%4,%5,%6,%7}, {%8,%9}, {%0,%1,%2,%3};"
        : "+f"(c[0]), "+f"(c[1]), "+f"(c[2]), "+f"(c[3])
        : "r"(a[0]), "r"(a[1]), "r"(a[2]), "r"(a[3]),
          "r"(b[0]), "r"(b[1]));
}

// ---------------- merged prologue: x -> fp16 ; W^T (masked, diag^2) -> fp16 -
// grid: [0, XBLOCKS) -> x blocks (1 float4/thread); then WBLOCKS w blocks.
__global__ __launch_bounds__(256) void prologue_kernel(
    const float4* __restrict__ x,
    const float* __restrict__ tw, const float* __restrict__ bbw)
{
    if (blockIdx.x < XBLOCKS) {
        const size_t i = (size_t)blockIdx.x * 256 + threadIdx.x;
        const float4 v = x[i];
        uint2 H;
        H.x = pk2(__float2half_rn(v.x), __float2half_rn(v.y));
        H.y = pk2(__float2half_rn(v.z), __float2half_rn(v.w));
        ((uint2*)g_xh)[i] = H;
    } else {
        __shared__ float sw[32][33];
        const int bid = blockIdx.x - XBLOCKS;
        const int n0 = (bid & 127) * 32;       // column-tile
        const int k0 = (bid >> 7) * 32;        // k-tile
        const int tx = threadIdx.x & 31;
        const int ty = threadIdx.x >> 5;       // 0..7

        #pragma unroll
        for (int r = 0; r < 4; r++) {
            const int k = k0 + ty + r * 8;
            const int n = n0 + tx;
            const int kb = k >> 6, nb = n >> 6;
            float w = 0.0f;
            if (kb == nb)      { const float t = tw[(size_t)k * DIM + n]; w = t * t; }
            else if (kb < nb)  { w = bbw[(size_t)k * DIM + n]; }
            sw[ty + r * 8][tx] = w;
        }
        __syncthreads();
        #pragma unroll
        for (int r = 0; r < 4; r++) {
            const int n = n0 + ty + r * 8;
            const int k = k0 + tx;
            g_whT[(size_t)n * DIM + k] = __float2half_rn(sw[tx][ty + r * 8]);
        }
    }
}

// ---------------- fp16 GEMM + fused column stats ----------------------------
// Grid (NT, MT). CTA 128x128, 128 threads (4 warps), warp tile 64x64.
// BK=32, 4-stage cp.async pipeline (1 sync/k-tile), 2 CTAs/SM.
// Per ks: ALL 8 LDSM4 issued back-to-back, then 64 mma (hides LDS latency).
// Epilogue: h = c + x_init (f32) -> stats (f32) + g_hh (fp16), fixed slots
// g_psum/g_psumsq[rg = mt*2 + (wid>>1)] (deterministic).
__global__ __launch_bounds__(128, 2) void gemm_mma_kernel(const float* __restrict__ x_init)
{
    extern __shared__ char smc[];
    const uint32_t smb = smem_u32(smc);

    const int tid = threadIdx.x;
    const int wid = tid >> 5;
    const int lid = tid & 31;
    const int lane4 = lid >> 2;     // 0..7
    const int laneq = lid & 3;      // 0..3

    const int nt = (NT - 1) - blockIdx.x;   // heavy tiles first
    const int mt = blockIdx.y;
    const int m0 = mt * BM;
    const int n0 = nt * BN;
    const int KT = (nt + 1) * 4;    // k-tiles of 32

    const int m0w = (wid >> 1) * 64;
    const int n0w = (wid & 1) * 64;

    float c[4][8][4];
    #pragma unroll
    for (int i = 0; i < 4; i++)
        #pragma unroll
        for (int j = 0; j < 8; j++)
            #pragma unroll
            for (int q = 0; q < 4; q++)
                c[i][j][q] = 0.0f;

    // producer: 8 cp.async (16B) per thread per stage.
    auto issue_stage = [&](int kt, int s) {
        const int kof = kt * BK;
        const uint32_t sb = smb + (uint32_t)s * STAGE_B;
        #pragma unroll
        for (int it = 0; it < 8; it++) {
            const int idx  = tid + it * 128;
            const int tile = idx >> 9;
            const int row  = (idx >> 2) & 127;
            const int ch   = idx & 3;
            const __half* base = tile ? g_whT : g_xh;
            const int row0     = tile ? n0 : m0;
            const __half* src = base + (size_t)(row0 + row) * DIM + kof + ch * 8;
            const uint32_t dst = sb + (uint32_t)(tile * TILE_B + row * ROWB + ch * 16);
            CPA16(dst, src);
        }
        CPA_COMMIT();
    };

    // per-thread ldmatrix offset components (byte offsets within a tile)
    const int L = lid;
    const uint32_t a_off = (uint32_t)((m0w + (L & 15)) * ROWB + (L >> 4) * 16);
    const uint32_t b_off = (uint32_t)((n0w + ((L >> 4) & 1) * 8 + (L & 7)) * ROWB
                                      + ((L >> 3) & 1) * 16);

    // prologue: fill 3 stages (KT >= 4 always)
    issue_stage(0, 0);
    issue_stage(1, 1);
    issue_stage(2, 2);

    int s  = 0;              // stage of k-tile kt
    int s3 = NSTAGE - 1;     // stage of k-tile kt+3
    for (int kt = 0; kt < KT; kt++) {
        const int rem = KT - kt - 1;
        if      (rem >= 2) { CPA_WAIT2(); }
        else if (rem == 1) { CPA_WAIT1(); }
        else               { CPA_WAIT0(); }
        __syncthreads();

        // refill the slot read at iteration kt-1 (safe behind the sync)
        if (kt + 3 < KT) issue_stage(kt + 3, s3);

        const uint32_t sb  = smb + (uint32_t)s * STAGE_B;
        const uint32_t sAh = sb;
        const uint32_t sBh = sb + TILE_B;

        #pragma unroll
        for (int ks = 0; ks < 2; ks++) {
            const uint32_t ko = (uint32_t)ks * 32;

            // ALL loads first: 4 B-LDSM4 + 4 A-LDSM4 back-to-back
            uint32_t bh[8][2];
            #pragma unroll
            for (int jp = 0; jp < 4; jp++) {
                const uint32_t bo = b_off + (uint32_t)jp * 16 * ROWB + ko;
                LDSM4(bh[jp*2][0], bh[jp*2][1], bh[jp*2+1][0], bh[jp*2+1][1], sBh + bo);
            }
            uint32_t ah[4][4];
            #pragma unroll
            for (int i = 0; i < 4; i++) {
                const uint32_t ao = a_off + (uint32_t)i * 16 * ROWB + ko;
                LDSM4(ah[i][0], ah[i][1], ah[i][2], ah[i][3], sAh + ao);
            }
            // then 64 mma with no interleaved loads
            #pragma unroll
            for (int i = 0; i < 4; i++)
                #pragma unroll
                for (int j = 0; j < 8; j++)
                    mma_fp16(c[i][j], ah[i], bh[j]);
        }

        s  = (s  == NSTAGE - 1) ? 0 : s  + 1;
        s3 = (s3 == NSTAGE - 1) ? 0 : s3 + 1;
    }

    // ---- epilogue: h = c + x_init (f32); stats in f32; store h as fp16 ----
    float cs[8][2], cq[8][2];
    #pragma unroll
    for (int j = 0; j < 8; j++) {
        cs[j][0] = 0.f; cs[j][1] = 0.f;
        cq[j][0] = 0.f; cq[j][1] = 0.f;
    }

    #pragma unroll
    for (int i = 0; i < 4; i++) {
        const int row = m0 + m0w + i * 16 + lane4;
        #pragma unroll
        for (int j = 0; j < 8; j++) {
            const int col = n0 + n0w + j * 8 + laneq * 2;
            const size_t o0 = (size_t)row * DIM + col;
            const size_t o1 = (size_t)(row + 8) * DIM + col;
            const float2 x0 = *(const float2*)(x_init + o0);
            const float2 x1 = *(const float2*)(x_init + o1);
            float2 v0, v1;
            v0.x = c[i][j][0] + x0.x;
            v0.y = c[i][j][1] + x0.y;
            v1.x = c[i][j][2] + x1.x;
            v1.y = c[i][j][3] + x1.y;
            *(__half2*)(g_hh + o0) = __floats2half2_rn(v0.x, v0.y);
            *(__half2*)(g_hh + o1) = __floats2half2_rn(v1.x, v1.y);
            cs[j][0] += v0.x + v1.x;
            cs[j][1] += v0.y + v1.y;
            cq[j][0] = fmaf(v0.x, v0.x, fmaf(v1.x, v1.x, cq[j][0]));
            cq[j][1] = fmaf(v0.y, v0.y, fmaf(v1.y, v1.y, cq[j][1]));
        }
    }

    // reduce over lane4 (8 lanes: xor 4, 8, 16); then lanes 0..3 write
    const int rg = mt * 2 + (wid >> 1);      // 64-row group id (0..127)
    #pragma unroll
    for (int j = 0; j < 8; j++) {
        #pragma unroll
        for (int b = 0; b < 2; b++) {
            float sv = cs[j][b], qv = cq[j][b];
            sv += __shfl_xor_sync(0xffffffffu, sv, 4);
            sv += __shfl_xor_sync(0xffffffffu, sv, 8);
            sv += __shfl_xor_sync(0xffffffffu, sv, 16);
            qv += __shfl_xor_sync(0xffffffffu, qv, 4);
            qv += __shfl_xor_sync(0xffffffffu, qv, 8);
            qv += __shfl_xor_sync(0xffffffffu, qv, 16);
            if (lane4 == 0) {
                const int col = n0 + n0w + j * 8 + laneq * 2 + b;
                g_psum[rg * DIM + col]   = sv;
                g_psumsq[rg * DIM + col] = qv;
            }
        }
    }
}

// ---------------- stats 2a: reduce 128 row-groups -> 8 ----------------------
__global__ __launch_bounds__(256) void stats2a_kernel()
{
    const int col = blockIdx.x * 256 + threadIdx.x;
    const int g   = blockIdx.y;                    // 0..7
    float s = 0.0f, q = 0.0f;
    #pragma unroll
    for (int r = 0; r < 16; r++) {
        const int rg = g * 16 + r;
        s += g_psum[rg * DIM + col];
        q += g_psumsq[rg * DIM + col];
    }
    g_psum2[g * DIM + col]   = s;
    g_psumsq2[g * DIM + col] = q;
}

// ---------------- stats 2b: finalize mean / scale ---------------------------
__global__ __launch_bounds__(256) void stats2b_kernel()
{
    const int col = blockIdx.x * 256 + threadIdx.x;
    float s = 0.0f, q = 0.0f;
    #pragma unroll
    for (int g = 0; g < 8; g++) {
        s += g_psum2[g * DIM + col];
        q += g_psumsq2[g * DIM + col];
    }
    const float inv_n = 1.0f / (float)B_ROWS;
    const float mean  = s * inv_n;
    float var = q * inv_n - mean * mean;
    var = fmaxf(var, 0.0f);
    g_mean[col]  = mean;
    g_scale[col] = 1.0f / (sqrtf(var) + EPS);
}

// ---------------- normalize + sigmoid (h read as fp16) ----------------------
__global__ __launch_bounds__(256) void final_kernel(float* __restrict__ out)
{
    const int row  = blockIdx.y;
    const int col  = (blockIdx.x * 256 + threadIdx.x) * 4;
    const size_t off = (size_t)row * DIM + col;

    const uint2 raw = *(const uint2*)(g_hh + off);
    const float2 h01 = __half22float2(*(const __half2*)&raw.x);
    const float2 h23 = __half22float2(*(const __half2*)&raw.y);
    const float4 mu = *(const float4*)(g_mean + col);
    const float4 sc = *(const float4*)(g_scale + col);

    float4 o;
    o.x = 1.0f / (1.0f + expf(-(h01.x - mu.x) * sc.x));
    o.y = 1.0f / (1.0f + expf(-(h01.y - mu.y) * sc.y));
    o.z = 1.0f / (1.0f + expf(-(h23.x - mu.z) * sc.z));
    o.w = 1.0f / (1.0f + expf(-(h23.y - mu.w) * sc.w));
    *(float4*)(out + off) = o;
}

// ---------------- launcher ---------------------------------------------------
extern "C" void kernel_launch(void* const* d_in, const int* in_sizes, int n_in,
                              void* d_out, int out_size)
{
    const float* x   = (const float*)d_in[0];
    const float* xi  = (const float*)d_in[1];
    const float* tw  = (const float*)d_in[2];
    const float* bbw = (const float*)d_in[3];
    float* out = (float*)d_out;

    cudaFuncSetAttribute(gemm_mma_kernel,
                         cudaFuncAttributeMaxDynamicSharedMemorySize, DYN_SMEM);

    prologue_kernel<<<XBLOCKS + WBLOCKS, 256>>>((const float4*)x, tw, bbw);
    gemm_mma_kernel<<<dim3(NT, MT), 128, DYN_SMEM>>>(xi);
    stats2a_kernel<<<dim3(16, 8), 256>>>();
    stats2b_kernel<<<16, 256>>>();
    final_kernel<<<dim3(DIM / (256 * 4), B_ROWS), 256>>>(out);
}